// round 8
// baseline (speedup 1.0000x reference)
#include <cuda_runtime.h>
#include <cuda_fp16.h>
#include <cuda_bf16.h>
#include <cstdint>

#define BB 64
#define HH 1024
#define TT 1024
#define VV 32000
#define NCHUNK 16
#define TPC (TT / NCHUNK)

// ---------------- scratch (no allocs allowed) ----------------
__device__ float g_scores[BB * TT];
__device__ float g_am[NCHUNK * BB];
__device__ float g_as[NCHUNK * BB];
__device__ float g_cctx[NCHUNK * BB * HH];
__device__ float g_cpart[4 * BB * VV];                     // 32.8MB partials
__device__ __half g_emb[BB * HH];
__device__ __half g_hid[BB * HH];
__device__ __half g_cin[BB * 2 * HH];
__device__ __half g_cout[BB * HH];

// ---------------- helpers ----------------
// split two fp32 into fp16 hi pair + fp16 residual pair
__device__ __forceinline__ void splith2(float f0, float f1, uint32_t& hi, uint32_t& lo) {
    __half h0 = __float2half_rn(f0), h1 = __float2half_rn(f1);
    hi = (uint32_t)__half_as_ushort(h0) | ((uint32_t)__half_as_ushort(h1) << 16);
    __half l0 = __float2half_rn(f0 - __half2float(h0));
    __half l1 = __float2half_rn(f1 - __half2float(h1));
    lo = (uint32_t)__half_as_ushort(l0) | ((uint32_t)__half_as_ushort(l1) << 16);
}

#define MMA16816(D, A, B) \
    asm volatile("mma.sync.aligned.m16n8k16.row.col.f32.f16.f16.f32 " \
        "{%0,%1,%2,%3}, {%4,%5,%6,%7}, {%8,%9}, {%0,%1,%2,%3};" \
        : "+f"((D)[0]), "+f"((D)[1]), "+f"((D)[2]), "+f"((D)[3]) \
        : "r"((A)[0]), "r"((A)[1]), "r"((A)[2]), "r"((A)[3]), "r"((B)[0]), "r"((B)[1]))

// load 8 float2 of W for one 16-k chunk (both 16-row m-fragments)
#define LOADW(dst, kk) do { \
    _Pragma("unroll") \
    for (int mf = 0; mf < 2; mf++) { \
        const float* p = Wp + (size_t)mf * 16 * K + (kk); \
        (dst)[mf * 4 + 0] = *(const float2*)(p); \
        (dst)[mf * 4 + 1] = *(const float2*)(p + (size_t)8 * K); \
        (dst)[mf * 4 + 2] = *(const float2*)(p + 8); \
        (dst)[mf * 4 + 3] = *(const float2*)(p + (size_t)8 * K + 8); \
    } \
} while (0)

// load X fragments (single fp16) for one 16-k chunk
#define LOADX(xr, kk) do { \
    _Pragma("unroll") \
    for (int bf = 0; bf < 8; bf++) { \
        size_t off = (size_t)(bf * 8 + grp) * K + k0b + (kk) + qid * 2; \
        (xr)[bf][0] = *(const uint32_t*)(Xp + off); \
        (xr)[bf][1] = *(const uint32_t*)(Xp + off + 8); \
    } \
} while (0)

// split W buffer + 32 MMAs for one 16-k chunk
#define CHUNK_MMA(wsrc, xr) do { \
    uint32_t wh[2][4], wl[2][4]; \
    _Pragma("unroll") \
    for (int mf = 0; mf < 2; mf++) \
        _Pragma("unroll") \
        for (int j = 0; j < 4; j++) \
            splith2((wsrc)[mf * 4 + j].x, (wsrc)[mf * 4 + j].y, wh[mf][j], wl[mf][j]); \
    _Pragma("unroll") \
    for (int mf = 0; mf < 2; mf++) \
        _Pragma("unroll") \
        for (int bf = 0; bf < 8; bf++) { \
            MMA16816(acc[mf][bf], wh[mf], (xr)[bf]); \
            MMA16816(acc[mf][bf], wl[mf], (xr)[bf]); \
        } \
} while (0)

// ---------------- HMMA GEMM: Out[ksplit][b][n] = X[64,K] @ W[N,K]^T ----------------
// W fp32 -> fp16 hi/lo in-register; X single fp16. 2 MMA terms. kpb % 32 == 0.
__global__ void __launch_bounds__(128, 2) k_hmma(
    const float* __restrict__ W0, const float* __restrict__ W1,
    const __half* __restrict__ X0, const __half* __restrict__ X1,
    float* __restrict__ Out0, float* __restrict__ Out1,
    int K)
{
    const float* W = blockIdx.z ? W1 : W0;
    const __half* Xp = blockIdx.z ? X1 : X0;
    float* Out = blockIdx.z ? Out1 : Out0;

    const int Ntot = gridDim.x * 128;
    const int w = threadIdx.x >> 5, l = threadIdx.x & 31;
    const int grp = l >> 2, qid = l & 3;
    const int n0 = blockIdx.x * 128 + w * 32;
    const int kpb = K / gridDim.y;
    const int k0b = blockIdx.y * kpb;
    Out += (size_t)blockIdx.y * ((size_t)BB * Ntot);

    float acc[2][8][4] = {};
    const float* Wp = W + (size_t)(n0 + grp) * K + k0b + qid * 2;

    float2 wA[8], wB[8];
    uint32_t xA[8][2], xB[8][2];
    LOADW(wA, 0);
    LOADX(xA, 0);
    for (int kk = 0; kk < kpb; kk += 32) {
        if (kk + 16 < kpb) { LOADW(wB, kk + 16); LOADX(xB, kk + 16); }
        CHUNK_MMA(wA, xA);
        if (kk + 32 < kpb) { LOADW(wA, kk + 32); LOADX(xA, kk + 32); }
        CHUNK_MMA(wB, xB);
    }

#pragma unroll
    for (int mf = 0; mf < 2; mf++) {
        int n = n0 + mf * 16 + grp;
#pragma unroll
        for (int bf = 0; bf < 8; bf++) {
            int b = bf * 8 + qid * 2;
            Out[(size_t)b * Ntot + n]           = acc[mf][bf][0];
            Out[(size_t)(b + 1) * Ntot + n]     = acc[mf][bf][1];
            Out[(size_t)b * Ntot + n + 8]       = acc[mf][bf][2];
            Out[(size_t)(b + 1) * Ntot + n + 8] = acc[mf][bf][3];
        }
    }
}

// ---------------- prep: embedding gather + hidden -> fp16 ----------------
__global__ void k_prep(const int* __restrict__ seq, const float* __restrict__ table,
                       const float* __restrict__ last_hidden) {
    int i = blockIdx.x * 256 + threadIdx.x;   // B*H
    int b = i >> 10, h = i & 1023;
    g_emb[i] = __float2half_rn(table[(size_t)seq[b] * HH + h]);
    g_hid[i] = __float2half_rn(last_hidden[i]);
}

// ---------------- GRU gates (8-way partial combine + bias folded) ----------------
__global__ void k_gate(const float* __restrict__ last_hidden, float* __restrict__ out_hidden,
                       const float* __restrict__ b_ih, const float* __restrict__ b_hh) {
    int i = blockIdx.x * 256 + threadIdx.x;   // B*H
    int b = i >> 10, h = i & 1023;
    const float* cpA = g_cpart;                        // gx partials [8][B][3H]
    const float* cpB = g_cpart + 8 * BB * 3 * HH;      // gh partials [8][B][3H]
    const int S = BB * 3 * HH;
    int base = b * 3 * HH;
    float xr = b_ih[h], xz = b_ih[HH + h], xn = b_ih[2 * HH + h];
    float hr = b_hh[h], hz = b_hh[HH + h], hn = b_hh[2 * HH + h];
#pragma unroll
    for (int s = 0; s < 8; s++) {
        xr += cpA[s * S + base + h];
        xz += cpA[s * S + base + HH + h];
        xn += cpA[s * S + base + 2 * HH + h];
        hr += cpB[s * S + base + h];
        hz += cpB[s * S + base + HH + h];
        hn += cpB[s * S + base + 2 * HH + h];
    }
    float r = 1.f / (1.f + expf(-(xr + hr)));
    float z = 1.f / (1.f + expf(-(xz + hz)));
    float n = tanhf(xn + r * hn);
    float hnew = (1.f - z) * n + z * last_hidden[i];
    out_hidden[i] = hnew;
    g_cin[b * 2 * HH + h] = __float2half_rn(hnew);
}

// ---------------- fused attention, 8-timestep batched online softmax ----------------
__global__ void __launch_bounds__(256) k_attn(const float* __restrict__ enc, const float* __restrict__ hnew) {
    int chunk = blockIdx.x, b = blockIdx.y;
    int tid = threadIdx.x;
    int wid = tid >> 5, lane = tid & 31;
    int h0 = tid * 4;
    __shared__ float red[8][8];       // [j][warp]
    __shared__ float score_sh[8];
    __shared__ float bc[9];           // rs, w[0..7]
    float4 hv = *(const float4*)&hnew[b * HH + h0];
    float m = -1e30f, s = 0.f;
    float c0 = 0.f, c1 = 0.f, c2 = 0.f, c3 = 0.f;
    int t0 = chunk * TPC;

    for (int tt = 0; tt < TPC; tt += 8) {
        float4 ev[8];
#pragma unroll
        for (int j = 0; j < 8; j++)
            ev[j] = *(const float4*)&enc[((size_t)(t0 + tt + j) * BB + b) * HH + h0];
        float p[8];
#pragma unroll
        for (int j = 0; j < 8; j++)
            p[j] = hv.x * ev[j].x + hv.y * ev[j].y + hv.z * ev[j].z + hv.w * ev[j].w;
#pragma unroll
        for (int o = 16; o; o >>= 1)
#pragma unroll
            for (int j = 0; j < 8; j++) p[j] += __shfl_xor_sync(0xffffffffu, p[j], o);
        if (lane == 0)
#pragma unroll
            for (int j = 0; j < 8; j++) red[j][wid] = p[j];
        __syncthreads();
        if (tid < 8) {
            float sc = red[tid][0] + red[tid][1] + red[tid][2] + red[tid][3]
                     + red[tid][4] + red[tid][5] + red[tid][6] + red[tid][7];
            score_sh[tid] = sc;
            g_scores[b * TT + t0 + tt + tid] = sc;
        }
        __syncthreads();
        if (tid == 0) {
            float bm = score_sh[0];
#pragma unroll
            for (int j = 1; j < 8; j++) bm = fmaxf(bm, score_sh[j]);
            float newm = fmaxf(m, bm);
            float rs = expf(m - newm);
            float ws = 0.f;
#pragma unroll
            for (int j = 0; j < 8; j++) { float wv = expf(score_sh[j] - newm); bc[1 + j] = wv; ws += wv; }
            s = s * rs + ws;
            m = newm;
            bc[0] = rs;
        }
        __syncthreads();
        float rs = bc[0];
        float w0 = bc[1], w1 = bc[2], w2 = bc[3], w3 = bc[4];
        float w4 = bc[5], w5 = bc[6], w6 = bc[7], w7 = bc[8];
        c0 = c0 * rs; c1 = c1 * rs; c2 = c2 * rs; c3 = c3 * rs;
        c0 += w0 * ev[0].x + w1 * ev[1].x + w2 * ev[2].x + w3 * ev[3].x
            + w4 * ev[4].x + w5 * ev[5].x + w6 * ev[6].x + w7 * ev[7].x;
        c1 += w0 * ev[0].y + w1 * ev[1].y + w2 * ev[2].y + w3 * ev[3].y
            + w4 * ev[4].y + w5 * ev[5].y + w6 * ev[6].y + w7 * ev[7].y;
        c2 += w0 * ev[0].z + w1 * ev[1].z + w2 * ev[2].z + w3 * ev[3].z
            + w4 * ev[4].z + w5 * ev[5].z + w6 * ev[6].z + w7 * ev[7].z;
        c3 += w0 * ev[0].w + w1 * ev[1].w + w2 * ev[2].w + w3 * ev[3].w
            + w4 * ev[4].w + w5 * ev[5].w + w6 * ev[6].w + w7 * ev[7].w;
        __syncthreads();   // protect red[][] reuse next iteration
    }
    *(float4*)&g_cctx[((size_t)chunk * BB + b) * HH + h0] = make_float4(c0, c1, c2, c3);
    if (tid == 0) { g_am[chunk * BB + b] = m; g_as[chunk * BB + b] = s; }
}

// ---------------- attention combine: merge partials, emit attn + fp16 context ----------------
__global__ void k_attn_comb(float* __restrict__ attn_out) {
    int b = blockIdx.x;
    int tid = threadIdx.x;
    float f[NCHUNK];
    float mstar = -1e30f;
#pragma unroll
    for (int c = 0; c < NCHUNK; c++) mstar = fmaxf(mstar, g_am[c * BB + b]);
    float sstar = 0.f;
#pragma unroll
    for (int c = 0; c < NCHUNK; c++) {
        f[c] = expf(g_am[c * BB + b] - mstar);
        sstar += g_as[c * BB + b] * f[c];
    }
    float inv = 1.f / sstar;
    int h0 = tid * 4;
    float a[4] = {0.f, 0.f, 0.f, 0.f};
#pragma unroll
    for (int c = 0; c < NCHUNK; c++) {
        float4 v = *(const float4*)&g_cctx[((size_t)c * BB + b) * HH + h0];
        a[0] += v.x * f[c]; a[1] += v.y * f[c]; a[2] += v.z * f[c]; a[3] += v.w * f[c];
    }
#pragma unroll
    for (int j = 0; j < 4; j++)
        g_cin[b * 2 * HH + HH + h0 + j] = __float2half_rn(a[j] * inv);
#pragma unroll
    for (int j = 0; j < 4; j++) {
        int t = tid + j * 256;
        attn_out[b * TT + t] = expf(g_scores[b * TT + t] - mstar) * inv;
    }
}

// ---------------- concat combine: sum 16 partials + bias -> tanh -> fp16 ----------------
__global__ void k_comb_concat(const float* __restrict__ concat_b) {
    int i = blockIdx.x * 256 + threadIdx.x;   // B*H
    int n = i & 1023;
    float v = concat_b[n];
#pragma unroll
    for (int s = 0; s < 16; s++) v += g_cpart[s * BB * HH + i];
    g_cout[i] = __float2half_rn(tanhf(v));
}

// ---------------- out combine: 4 partials + bias ----------------
__global__ void k_comb_out(const float* __restrict__ out_b, float* __restrict__ out) {
    int i = blockIdx.x * 256 + threadIdx.x;   // B*V
    int n = i % VV;
    const size_t S = (size_t)BB * VV;
    out[i] = ((g_cpart[i] + g_cpart[S + i]) + (g_cpart[2 * S + i] + g_cpart[3 * S + i])) + out_b[n];
}

// ---------------- launcher ----------------
extern "C" void kernel_launch(void* const* d_in, const int* in_sizes, int n_in,
                              void* d_out, int out_size) {
    const int*   seq         = (const int*)d_in[0];
    const float* last_hidden = (const float*)d_in[1];
    const float* enc         = (const float*)d_in[2];
    const float* emb_table   = (const float*)d_in[3];
    const float* w_ih        = (const float*)d_in[4];
    const float* w_hh        = (const float*)d_in[5];
    const float* b_ih        = (const float*)d_in[6];
    const float* b_hh        = (const float*)d_in[7];
    const float* concat_W    = (const float*)d_in[8];
    const float* concat_b    = (const float*)d_in[9];
    const float* out_W       = (const float*)d_in[10];
    const float* out_b       = (const float*)d_in[11];

    float* out        = (float*)d_out;             // [B, V]
    float* out_hidden = out + BB * VV;             // [1, B, H]
    float* out_attn   = out + BB * VV + BB * HH;   // [B, 1, T]

    float* p_cp;
    __half *p_emb, *p_hid, *p_cin, *p_cout;
    cudaGetSymbolAddress((void**)&p_cp,   g_cpart);
    cudaGetSymbolAddress((void**)&p_emb,  g_emb);
    cudaGetSymbolAddress((void**)&p_hid,  g_hid);
    cudaGetSymbolAddress((void**)&p_cin,  g_cin);
    cudaGetSymbolAddress((void**)&p_cout, g_cout);

    float* cpA = p_cp;                                // gx partials [8][B][3H]
    float* cpB = p_cp + 8 * BB * 3 * HH;              // gh partials [8][B][3H]

    // 1. prep: embedding + hidden -> fp16
    k_prep<<<256, 256>>>(seq, emb_table, last_hidden);
    // 2. gx = emb @ w_ih^T ; gh = h @ w_hh^T  (merged via z, ksplit=8 -> 384 CTAs)
    k_hmma<<<dim3(24, 8, 2), 128>>>(w_ih, w_hh, p_emb, p_hid, cpA, cpB, HH);
    // 3. GRU gates -> h_new (folds 8-way partial-combine + bias)
    k_gate<<<256, 256>>>(last_hidden, out_hidden, b_ih, b_hh);
    // 4. fused attention, single enc pass (batched online softmax)
    k_attn<<<dim3(NCHUNK, BB), 256>>>(enc, out_hidden);
    k_attn_comb<<<BB, 256>>>(out_attn);
    // 5. concat gemm (K=2048, ksplit=16 -> 128 CTAs)
    k_hmma<<<dim3(8, 16, 1), 128>>>(concat_W, concat_W, p_cin, p_cin, p_cp, p_cp, 2 * HH);
    k_comb_concat<<<256, 256>>>(concat_b);
    // 6. output gemm (K=1024, ksplit=4 -> 1000 CTAs) + combine
    k_hmma<<<dim3(250, 4, 1), 128>>>(out_W, out_W, p_cout, p_cout, p_cp, p_cp, HH);
    k_comb_out<<<8000, 256>>>(out_b, out);
}

// round 9
// speedup vs baseline: 1.0494x; 1.0494x over previous
#include <cuda_runtime.h>
#include <cuda_bf16.h>
#include <cstdint>

#define BB 64
#define HH 1024
#define TT 1024
#define VV 32000
#define NCHUNK 16
#define TPC (TT / NCHUNK)

// ---------------- scratch (no allocs allowed) ----------------
__device__ float g_scores[BB * TT];
__device__ float g_am[NCHUNK * BB];
__device__ float g_as[NCHUNK * BB];
__device__ float g_cctx[NCHUNK * BB * HH];
__device__ float g_cpart[4 * BB * VV];                 // 32.8MB partials
__device__ uint2 g_xemb[BB * HH / 2];                  // interleaved {bf16x2 hi, bf16x2 lo}
__device__ uint2 g_xhid[BB * HH / 2];
__device__ uint2 g_xcin[BB * 2 * HH / 2];
__device__ uint2 g_xcout[BB * HH / 2];

// ---------------- helpers ----------------
// split two fp32 into bf16x2 hi pair + bf16x2 residual pair
__device__ __forceinline__ void split2(float f0, float f1, uint32_t& hi, uint32_t& lo) {
    uint32_t h0 = (uint32_t)__bfloat16_as_ushort(__float2bfloat16(f0));
    uint32_t h1 = (uint32_t)__bfloat16_as_ushort(__float2bfloat16(f1));
    hi = h0 | (h1 << 16);
    float r0 = f0 - __uint_as_float(h0 << 16);
    float r1 = f1 - __uint_as_float(h1 << 16);
    uint32_t l0 = (uint32_t)__bfloat16_as_ushort(__float2bfloat16(r0));
    uint32_t l1 = (uint32_t)__bfloat16_as_ushort(__float2bfloat16(r1));
    lo = l0 | (l1 << 16);
}

#define MMA16816(D, A, B) \
    asm volatile("mma.sync.aligned.m16n8k16.row.col.f32.bf16.bf16.f32 " \
        "{%0,%1,%2,%3}, {%4,%5,%6,%7}, {%8,%9}, {%0,%1,%2,%3};" \
        : "+f"((D)[0]), "+f"((D)[1]), "+f"((D)[2]), "+f"((D)[3]) \
        : "r"((A)[0]), "r"((A)[1]), "r"((A)[2]), "r"((A)[3]), "r"((B)[0]), "r"((B)[1]))

// load 4 float2 of W for one 16-k chunk (16-row warp tile)
#define LOADW(dst, kk) do { \
    const float* p = Wp + (kk); \
    (dst)[0] = *(const float2*)(p); \
    (dst)[1] = *(const float2*)(p + (size_t)8 * K); \
    (dst)[2] = *(const float2*)(p + 8); \
    (dst)[3] = *(const float2*)(p + (size_t)8 * K + 8); \
} while (0)

// load X fragments (interleaved hi/lo) for one 16-k chunk: 16 LDG.64
#define LOADX(xh, xl, kk) do { \
    _Pragma("unroll") \
    for (int bf = 0; bf < 8; bf++) { \
        size_t pidx = (size_t)(bf * 8 + grp) * K2 + ((k0b + (kk)) >> 1) + qid; \
        uint2 u0 = Xp[pidx]; \
        uint2 u1 = Xp[pidx + 4]; \
        (xh)[bf][0] = u0.x; (xl)[bf][0] = u0.y; \
        (xh)[bf][1] = u1.x; (xl)[bf][1] = u1.y; \
    } \
} while (0)

// split W buffer + 24 MMAs (3-term) for one 16-k chunk
#define CHUNK_MMA(wsrc, xh, xl) do { \
    uint32_t ah[4], al[4]; \
    _Pragma("unroll") \
    for (int j = 0; j < 4; j++) \
        split2((wsrc)[j].x, (wsrc)[j].y, ah[j], al[j]); \
    _Pragma("unroll") \
    for (int bf = 0; bf < 8; bf++) { \
        MMA16816(acc[bf], ah, (xh)[bf]); \
        MMA16816(acc[bf], ah, (xl)[bf]); \
        MMA16816(acc[bf], al, (xh)[bf]); \
    } \
} while (0)

// ---------------- HMMA GEMM: Out[ksplit][b][n] = X[64,K] @ W[N,K]^T ----------------
// 8 warps/CTA, warp tile 16n x 64b, W double-buffered, bf16 3-term split. kpb % 32 == 0.
__global__ void __launch_bounds__(256, 2) k_hmma(
    const float* __restrict__ W0, const float* __restrict__ W1,
    const uint2* __restrict__ X0, const uint2* __restrict__ X1,
    float* __restrict__ Out0, float* __restrict__ Out1,
    int K)
{
    const float* W = blockIdx.z ? W1 : W0;
    const uint2* Xp = blockIdx.z ? X1 : X0;
    float* Out = blockIdx.z ? Out1 : Out0;

    const int Ntot = gridDim.x * 128;
    const int K2 = K >> 1;
    const int w = threadIdx.x >> 5, l = threadIdx.x & 31;
    const int grp = l >> 2, qid = l & 3;
    const int n0 = blockIdx.x * 128 + w * 16;
    const int kpb = K / gridDim.y;
    const int k0b = blockIdx.y * kpb;
    Out += (size_t)blockIdx.y * ((size_t)BB * Ntot);

    float acc[8][4] = {};
    const float* Wp = W + (size_t)(n0 + grp) * K + k0b + qid * 2;

    float2 wA[4], wB[4];
    uint32_t xh[8][2], xl[8][2];
    LOADW(wA, 0);
    for (int kk = 0; kk < kpb; kk += 32) {
        LOADX(xh, xl, kk);
        if (kk + 16 < kpb) LOADW(wB, kk + 16);
        CHUNK_MMA(wA, xh, xl);
        LOADX(xh, xl, kk + 16);
        if (kk + 32 < kpb) LOADW(wA, kk + 32);
        CHUNK_MMA(wB, xh, xl);
    }

    {
        int n = n0 + grp;
#pragma unroll
        for (int bf = 0; bf < 8; bf++) {
            int b = bf * 8 + qid * 2;
            Out[(size_t)b * Ntot + n]           = acc[bf][0];
            Out[(size_t)(b + 1) * Ntot + n]     = acc[bf][1];
            Out[(size_t)b * Ntot + n + 8]       = acc[bf][2];
            Out[(size_t)(b + 1) * Ntot + n + 8] = acc[bf][3];
        }
    }
}

// ---------------- prep: embedding gather + hidden -> interleaved bf16 hi/lo pairs ----------------
__global__ void k_prep(const int* __restrict__ seq, const float* __restrict__ table,
                       const float* __restrict__ last_hidden) {
    int i = blockIdx.x * 256 + threadIdx.x;   // B*H/2 pairs
    int b = i >> 9, hp = i & 511;
    float2 e = *(const float2*)&table[(size_t)seq[b] * HH + hp * 2];
    uint2 v;
    split2(e.x, e.y, v.x, v.y);
    g_xemb[i] = v;
    float2 hd = *(const float2*)&last_hidden[b * HH + hp * 2];
    split2(hd.x, hd.y, v.x, v.y);
    g_xhid[i] = v;
}

// ---------------- GRU gates (8-way partial combine + bias folded), 2 h per thread ----------------
__global__ void k_gate(const float* __restrict__ last_hidden, float* __restrict__ out_hidden,
                       const float* __restrict__ b_ih, const float* __restrict__ b_hh) {
    int i = blockIdx.x * 256 + threadIdx.x;   // B*H/2
    int b = i >> 9, hp = i & 511;
    const float* cpA = g_cpart;                        // gx partials [8][B][3H]
    const float* cpB = g_cpart + 8 * BB * 3 * HH;      // gh partials [8][B][3H]
    const int S = BB * 3 * HH;
    int base = b * 3 * HH;
    float hnew2[2];
#pragma unroll
    for (int e = 0; e < 2; e++) {
        int h = hp * 2 + e;
        float xr = b_ih[h], xz = b_ih[HH + h], xn = b_ih[2 * HH + h];
        float hr = b_hh[h], hz = b_hh[HH + h], hn = b_hh[2 * HH + h];
#pragma unroll
        for (int s = 0; s < 8; s++) {
            xr += cpA[s * S + base + h];
            xz += cpA[s * S + base + HH + h];
            xn += cpA[s * S + base + 2 * HH + h];
            hr += cpB[s * S + base + h];
            hz += cpB[s * S + base + HH + h];
            hn += cpB[s * S + base + 2 * HH + h];
        }
        float r = 1.f / (1.f + expf(-(xr + hr)));
        float z = 1.f / (1.f + expf(-(xz + hz)));
        float n = tanhf(xn + r * hn);
        hnew2[e] = (1.f - z) * n + z * last_hidden[b * HH + h];
        out_hidden[b * HH + h] = hnew2[e];
    }
    uint2 v;
    split2(hnew2[0], hnew2[1], v.x, v.y);
    g_xcin[b * 1024 + hp] = v;     // cin row = 2H -> 1024 pairs; first half
}

// ---------------- fused attention, 8-timestep batched online softmax ----------------
__global__ void __launch_bounds__(256) k_attn(const float* __restrict__ enc, const float* __restrict__ hnew) {
    int chunk = blockIdx.x, b = blockIdx.y;
    int tid = threadIdx.x;
    int wid = tid >> 5, lane = tid & 31;
    int h0 = tid * 4;
    __shared__ float red[8][8];       // [j][warp]
    __shared__ float score_sh[8];
    __shared__ float bc[9];           // rs, w[0..7]
    float4 hv = *(const float4*)&hnew[b * HH + h0];
    float m = -1e30f, s = 0.f;
    float c0 = 0.f, c1 = 0.f, c2 = 0.f, c3 = 0.f;
    int t0 = chunk * TPC;

    for (int tt = 0; tt < TPC; tt += 8) {
        float4 ev[8];
#pragma unroll
        for (int j = 0; j < 8; j++)
            ev[j] = *(const float4*)&enc[((size_t)(t0 + tt + j) * BB + b) * HH + h0];
        float p[8];
#pragma unroll
        for (int j = 0; j < 8; j++)
            p[j] = hv.x * ev[j].x + hv.y * ev[j].y + hv.z * ev[j].z + hv.w * ev[j].w;
#pragma unroll
        for (int o = 16; o; o >>= 1)
#pragma unroll
            for (int j = 0; j < 8; j++) p[j] += __shfl_xor_sync(0xffffffffu, p[j], o);
        if (lane == 0)
#pragma unroll
            for (int j = 0; j < 8; j++) red[j][wid] = p[j];
        __syncthreads();
        if (tid < 8) {
            float sc = red[tid][0] + red[tid][1] + red[tid][2] + red[tid][3]
                     + red[tid][4] + red[tid][5] + red[tid][6] + red[tid][7];
            score_sh[tid] = sc;
            g_scores[b * TT + t0 + tt + tid] = sc;
        }
        __syncthreads();
        if (tid == 0) {
            float bm = score_sh[0];
#pragma unroll
            for (int j = 1; j < 8; j++) bm = fmaxf(bm, score_sh[j]);
            float newm = fmaxf(m, bm);
            float rs = expf(m - newm);
            float ws = 0.f;
#pragma unroll
            for (int j = 0; j < 8; j++) { float wv = expf(score_sh[j] - newm); bc[1 + j] = wv; ws += wv; }
            s = s * rs + ws;
            m = newm;
            bc[0] = rs;
        }
        __syncthreads();
        float rs = bc[0];
        float w0 = bc[1], w1 = bc[2], w2 = bc[3], w3 = bc[4];
        float w4 = bc[5], w5 = bc[6], w6 = bc[7], w7 = bc[8];
        c0 = c0 * rs; c1 = c1 * rs; c2 = c2 * rs; c3 = c3 * rs;
        c0 += w0 * ev[0].x + w1 * ev[1].x + w2 * ev[2].x + w3 * ev[3].x
            + w4 * ev[4].x + w5 * ev[5].x + w6 * ev[6].x + w7 * ev[7].x;
        c1 += w0 * ev[0].y + w1 * ev[1].y + w2 * ev[2].y + w3 * ev[3].y
            + w4 * ev[4].y + w5 * ev[5].y + w6 * ev[6].y + w7 * ev[7].y;
        c2 += w0 * ev[0].z + w1 * ev[1].z + w2 * ev[2].z + w3 * ev[3].z
            + w4 * ev[4].z + w5 * ev[5].z + w6 * ev[6].z + w7 * ev[7].z;
        c3 += w0 * ev[0].w + w1 * ev[1].w + w2 * ev[2].w + w3 * ev[3].w
            + w4 * ev[4].w + w5 * ev[5].w + w6 * ev[6].w + w7 * ev[7].w;
        __syncthreads();   // protect red[][] reuse next iteration
    }
    *(float4*)&g_cctx[((size_t)chunk * BB + b) * HH + h0] = make_float4(c0, c1, c2, c3);
    if (tid == 0) { g_am[chunk * BB + b] = m; g_as[chunk * BB + b] = s; }
}

// ---------------- attention combine: merge partials, emit attn + interleaved context ----------------
__global__ void k_attn_comb(float* __restrict__ attn_out) {
    int b = blockIdx.x;
    int tid = threadIdx.x;
    float f[NCHUNK];
    float mstar = -1e30f;
#pragma unroll
    for (int c = 0; c < NCHUNK; c++) mstar = fmaxf(mstar, g_am[c * BB + b]);
    float sstar = 0.f;
#pragma unroll
    for (int c = 0; c < NCHUNK; c++) {
        f[c] = expf(g_am[c * BB + b] - mstar);
        sstar += g_as[c * BB + b] * f[c];
    }
    float inv = 1.f / sstar;
    int h0 = tid * 4;
    float a[4] = {0.f, 0.f, 0.f, 0.f};
#pragma unroll
    for (int c = 0; c < NCHUNK; c++) {
        float4 v = *(const float4*)&g_cctx[((size_t)c * BB + b) * HH + h0];
        a[0] += v.x * f[c]; a[1] += v.y * f[c]; a[2] += v.z * f[c]; a[3] += v.w * f[c];
    }
    uint2 v0, v1;
    split2(a[0] * inv, a[1] * inv, v0.x, v0.y);
    split2(a[2] * inv, a[3] * inv, v1.x, v1.y);
    g_xcin[b * 1024 + 512 + tid * 2]     = v0;   // second half (context), pair idx H/2 + h0/2
    g_xcin[b * 1024 + 512 + tid * 2 + 1] = v1;
#pragma unroll
    for (int j = 0; j < 4; j++) {
        int t = tid + j * 256;
        attn_out[b * TT + t] = expf(g_scores[b * TT + t] - mstar) * inv;
    }
}

// ---------------- concat combine: sum 16 partials + bias -> tanh -> interleaved pairs ----------------
__global__ void k_comb_concat(const float* __restrict__ concat_b) {
    int i = blockIdx.x * 256 + threadIdx.x;   // B*H/2
    float v2[2];
#pragma unroll
    for (int e = 0; e < 2; e++) {
        int idx = i * 2 + e;
        int n = idx & 1023;
        float v = concat_b[n];
#pragma unroll
        for (int s = 0; s < 16; s++) v += g_cpart[s * BB * HH + idx];
        v2[e] = tanhf(v);
    }
    uint2 v;
    split2(v2[0], v2[1], v.x, v.y);
    g_xcout[i] = v;
}

// ---------------- out combine: 4 partials + bias ----------------
__global__ void k_comb_out(const float* __restrict__ out_b, float* __restrict__ out) {
    int i = blockIdx.x * 256 + threadIdx.x;   // B*V
    int n = i % VV;
    const size_t S = (size_t)BB * VV;
    out[i] = ((g_cpart[i] + g_cpart[S + i]) + (g_cpart[2 * S + i] + g_cpart[3 * S + i])) + out_b[n];
}

// ---------------- launcher ----------------
extern "C" void kernel_launch(void* const* d_in, const int* in_sizes, int n_in,
                              void* d_out, int out_size) {
    const int*   seq         = (const int*)d_in[0];
    const float* last_hidden = (const float*)d_in[1];
    const float* enc         = (const float*)d_in[2];
    const float* emb_table   = (const float*)d_in[3];
    const float* w_ih        = (const float*)d_in[4];
    const float* w_hh        = (const float*)d_in[5];
    const float* b_ih        = (const float*)d_in[6];
    const float* b_hh        = (const float*)d_in[7];
    const float* concat_W    = (const float*)d_in[8];
    const float* concat_b    = (const float*)d_in[9];
    const float* out_W       = (const float*)d_in[10];
    const float* out_b       = (const float*)d_in[11];

    float* out        = (float*)d_out;             // [B, V]
    float* out_hidden = out + BB * VV;             // [1, B, H]
    float* out_attn   = out + BB * VV + BB * HH;   // [B, 1, T]

    float* p_cp;
    uint2 *p_xemb, *p_xhid, *p_xcin, *p_xcout;
    cudaGetSymbolAddress((void**)&p_cp,    g_cpart);
    cudaGetSymbolAddress((void**)&p_xemb,  g_xemb);
    cudaGetSymbolAddress((void**)&p_xhid,  g_xhid);
    cudaGetSymbolAddress((void**)&p_xcin,  g_xcin);
    cudaGetSymbolAddress((void**)&p_xcout, g_xcout);

    float* cpA = p_cp;                                // gx partials [8][B][3H]
    float* cpB = p_cp + 8 * BB * 3 * HH;              // gh partials [8][B][3H]

    // 1. prep: embedding + hidden -> interleaved bf16 hi/lo
    k_prep<<<128, 256>>>(seq, emb_table, last_hidden);
    // 2. gx = emb @ w_ih^T ; gh = h @ w_hh^T  (merged via z, ksplit=8 -> 384 CTAs)
    k_hmma<<<dim3(24, 8, 2), 256>>>(w_ih, w_hh, p_xemb, p_xhid, cpA, cpB, HH);
    // 3. GRU gates -> h_new (folds 8-way partial-combine + bias)
    k_gate<<<128, 256>>>(last_hidden, out_hidden, b_ih, b_hh);
    // 4. fused attention, single enc pass (batched online softmax)
    k_attn<<<dim3(NCHUNK, BB), 256>>>(enc, out_hidden);
    k_attn_comb<<<BB, 256>>>(out_attn);
    // 5. concat gemm (K=2048, ksplit=16 -> 128 CTAs)
    k_hmma<<<dim3(8, 16, 1), 256>>>(concat_W, concat_W, p_xcin, p_xcin, p_cp, p_cp, 2 * HH);
    k_comb_concat<<<128, 256>>>(concat_b);
    // 6. output gemm (K=1024, ksplit=4 -> 1000 CTAs) + combine
    k_hmma<<<dim3(250, 4, 1), 256>>>(out_W, out_W, p_xcout, p_xcout, p_cp, p_cp, HH);
    k_comb_out<<<8000, 256>>>(out_b, out);
}

// round 10
// speedup vs baseline: 1.2035x; 1.1469x over previous
#include <cuda_runtime.h>
#include <cuda_bf16.h>
#include <cstdint>

#define BB 64
#define HH 1024
#define TT 1024
#define VV 32000
#define NCHUNK 16
#define TPC (TT / NCHUNK)

// ---------------- scratch (no allocs allowed) ----------------
__device__ float g_scores[BB * TT];
__device__ float g_am[NCHUNK * BB];
__device__ float g_as[NCHUNK * BB];
__device__ float g_cctx[NCHUNK * BB * HH];
__device__ float g_cpart[4 * BB * VV];                 // 32.8MB partials
__device__ uint2 g_xemb[BB * HH / 2];                  // interleaved {bf16x2 hi, bf16x2 lo}
__device__ uint2 g_xhid[BB * HH / 2];
__device__ uint2 g_xcin[BB * 2 * HH / 2];
__device__ uint2 g_xcout[BB * HH / 2];

// ---------------- helpers ----------------
__device__ __forceinline__ void split2(float f0, float f1, uint32_t& hi, uint32_t& lo) {
    uint32_t h0 = (uint32_t)__bfloat16_as_ushort(__float2bfloat16(f0));
    uint32_t h1 = (uint32_t)__bfloat16_as_ushort(__float2bfloat16(f1));
    hi = h0 | (h1 << 16);
    float r0 = f0 - __uint_as_float(h0 << 16);
    float r1 = f1 - __uint_as_float(h1 << 16);
    uint32_t l0 = (uint32_t)__bfloat16_as_ushort(__float2bfloat16(r0));
    uint32_t l1 = (uint32_t)__bfloat16_as_ushort(__float2bfloat16(r1));
    lo = l0 | (l1 << 16);
}

#define MMA16816(D, A, B) \
    asm volatile("mma.sync.aligned.m16n8k16.row.col.f32.bf16.bf16.f32 " \
        "{%0,%1,%2,%3}, {%4,%5,%6,%7}, {%8,%9}, {%0,%1,%2,%3};" \
        : "+f"((D)[0]), "+f"((D)[1]), "+f"((D)[2]), "+f"((D)[3]) \
        : "r"((A)[0]), "r"((A)[1]), "r"((A)[2]), "r"((A)[3]), "r"((B)[0]), "r"((B)[1]))

// load 4 float2 of W for one 16-k chunk (16-row warp tile)
#define LOADW(dst, kk) do { \
    const float* p = Wp + (kk); \
    (dst)[0] = *(const float2*)(p); \
    (dst)[1] = *(const float2*)(p + (size_t)8 * K); \
    (dst)[2] = *(const float2*)(p + 8); \
    (dst)[3] = *(const float2*)(p + (size_t)8 * K + 8); \
} while (0)

// global X load: one uint4 (16B) per thread per chunk
#define LDGX(c) (*(const uint4*)&Xp[(size_t)(threadIdx.x >> 2) * K2 + ((k0b + (c) * 16) >> 1) + (threadIdx.x & 3) * 2])

// scatter a chunk's uint4 into fragment-order smem: sb[buf][bf*32 + lane] = that lane's uint4
#define STSX(pb, v) do { \
    int row_ = threadIdx.x >> 2, p4_ = threadIdx.x & 3; \
    int bf_ = row_ >> 3, grp_ = row_ & 7; \
    uint2* b_ = (uint2*)&sb[pb][0]; \
    if (p4_ < 2) { \
        int L_ = bf_ * 32 + grp_ * 4 + p4_ * 2; \
        b_[L_ * 2]       = make_uint2((v).x, (v).y); \
        b_[(L_ + 1) * 2] = make_uint2((v).z, (v).w); \
    } else { \
        int L_ = bf_ * 32 + grp_ * 4 + (p4_ - 2) * 2; \
        b_[L_ * 2 + 1]       = make_uint2((v).x, (v).y); \
        b_[(L_ + 1) * 2 + 1] = make_uint2((v).z, (v).w); \
    } \
} while (0)

// LDS fragments + split W + 24 MMAs (3-term) for one 16-k chunk
#define CHUNK_MMA_S(wsrc, pb) do { \
    uint32_t xh[8][2], xl[8][2]; \
    _Pragma("unroll") \
    for (int bf = 0; bf < 8; bf++) { \
        uint4 v_ = sb[pb][bf * 32 + l]; \
        xh[bf][0] = v_.x; xl[bf][0] = v_.y; \
        xh[bf][1] = v_.z; xl[bf][1] = v_.w; \
    } \
    uint32_t ah[4], al[4]; \
    _Pragma("unroll") \
    for (int j = 0; j < 4; j++) \
        split2((wsrc)[j].x, (wsrc)[j].y, ah[j], al[j]); \
    _Pragma("unroll") \
    for (int bf = 0; bf < 8; bf++) { \
        MMA16816(acc[bf], ah, xh[bf]); \
        MMA16816(acc[bf], ah, xl[bf]); \
        MMA16816(acc[bf], al, xh[bf]); \
    } \
} while (0)

// ---------------- HMMA GEMM: Out[ksplit][b][n] = X[64,K] @ W[N,K]^T ----------------
// 8 warps/CTA, warp tile 16n x 64b. X staged once per CTA per chunk through smem
// (fragment-order layout, 2-deep pipeline); W register-double-buffered. kpb % 32 == 0.
__global__ void __launch_bounds__(256, 2) k_hmma(
    const float* __restrict__ W0, const float* __restrict__ W1,
    const uint2* __restrict__ X0, const uint2* __restrict__ X1,
    float* __restrict__ Out0, float* __restrict__ Out1,
    int K)
{
    __shared__ uint4 sb[2][256];   // 2 x 4KB chunk buffers, fragment order
    const float* W = blockIdx.z ? W1 : W0;
    const uint2* Xp = blockIdx.z ? X1 : X0;
    float* Out = blockIdx.z ? Out1 : Out0;

    const int Ntot = gridDim.x * 128;
    const int K2 = K >> 1;
    const int w = threadIdx.x >> 5, l = threadIdx.x & 31;
    const int grp = l >> 2, qid = l & 3;
    const int n0 = blockIdx.x * 128 + w * 16;
    const int kpb = K / gridDim.y;
    const int k0b = blockIdx.y * kpb;
    const int nc = kpb >> 4;
    Out += (size_t)blockIdx.y * ((size_t)BB * Ntot);

    float acc[8][4] = {};
    const float* Wp = W + (size_t)(n0 + grp) * K + k0b + qid * 2;

    float2 wcur[4], wnxt[4];
    uint4 xnxt;
    {
        uint4 x0 = LDGX(0);
        STSX(0, x0);
        xnxt = (nc > 1) ? LDGX(1) : x0;
    }
    LOADW(wcur, 0);
    __syncthreads();

    for (int c = 0; c < nc; c++) {
        const int pb = c & 1;
        if (c + 1 < nc) STSX(pb ^ 1, xnxt);
        if (c + 2 < nc) xnxt = LDGX(c + 2);
        if (c + 1 < nc) LOADW(wnxt, (c + 1) * 16);
        CHUNK_MMA_S(wcur, pb);
#pragma unroll
        for (int j = 0; j < 4; j++) wcur[j] = wnxt[j];
        __syncthreads();
    }

    {
        int n = n0 + grp;
#pragma unroll
        for (int bf = 0; bf < 8; bf++) {
            int b = bf * 8 + qid * 2;
            Out[(size_t)b * Ntot + n]           = acc[bf][0];
            Out[(size_t)(b + 1) * Ntot + n]     = acc[bf][1];
            Out[(size_t)b * Ntot + n + 8]       = acc[bf][2];
            Out[(size_t)(b + 1) * Ntot + n + 8] = acc[bf][3];
        }
    }
}

// ---------------- prep: embedding gather + hidden -> interleaved bf16 hi/lo pairs ----------------
__global__ void k_prep(const int* __restrict__ seq, const float* __restrict__ table,
                       const float* __restrict__ last_hidden) {
    int i = blockIdx.x * 256 + threadIdx.x;   // B*H/2 pairs
    int b = i >> 9, hp = i & 511;
    float2 e = *(const float2*)&table[(size_t)seq[b] * HH + hp * 2];
    uint2 v;
    split2(e.x, e.y, v.x, v.y);
    g_xemb[i] = v;
    float2 hd = *(const float2*)&last_hidden[b * HH + hp * 2];
    split2(hd.x, hd.y, v.x, v.y);
    g_xhid[i] = v;
}

// ---------------- GRU gates (8-way partial combine + bias folded), 2 h per thread ----------------
__global__ void k_gate(const float* __restrict__ last_hidden, float* __restrict__ out_hidden,
                       const float* __restrict__ b_ih, const float* __restrict__ b_hh) {
    int i = blockIdx.x * 256 + threadIdx.x;   // B*H/2
    int b = i >> 9, hp = i & 511;
    const float* cpA = g_cpart;                        // gx partials [8][B][3H]
    const float* cpB = g_cpart + 8 * BB * 3 * HH;      // gh partials [8][B][3H]
    const int S = BB * 3 * HH;
    int base = b * 3 * HH;
    float hnew2[2];
#pragma unroll
    for (int e = 0; e < 2; e++) {
        int h = hp * 2 + e;
        float xr = b_ih[h], xz = b_ih[HH + h], xn = b_ih[2 * HH + h];
        float hr = b_hh[h], hz = b_hh[HH + h], hn = b_hh[2 * HH + h];
#pragma unroll
        for (int s = 0; s < 8; s++) {
            xr += cpA[s * S + base + h];
            xz += cpA[s * S + base + HH + h];
            xn += cpA[s * S + base + 2 * HH + h];
            hr += cpB[s * S + base + h];
            hz += cpB[s * S + base + HH + h];
            hn += cpB[s * S + base + 2 * HH + h];
        }
        float r = 1.f / (1.f + expf(-(xr + hr)));
        float z = 1.f / (1.f + expf(-(xz + hz)));
        float n = tanhf(xn + r * hn);
        hnew2[e] = (1.f - z) * n + z * last_hidden[b * HH + h];
        out_hidden[b * HH + h] = hnew2[e];
    }
    uint2 v;
    split2(hnew2[0], hnew2[1], v.x, v.y);
    g_xcin[b * 1024 + hp] = v;     // cin row = 2H -> 1024 pairs; first half
}

// ---------------- fused attention, 8-timestep batched online softmax ----------------
__global__ void __launch_bounds__(256) k_attn(const float* __restrict__ enc, const float* __restrict__ hnew) {
    int chunk = blockIdx.x, b = blockIdx.y;
    int tid = threadIdx.x;
    int wid = tid >> 5, lane = tid & 31;
    int h0 = tid * 4;
    __shared__ float red[8][8];       // [j][warp]
    __shared__ float score_sh[8];
    __shared__ float bc[9];           // rs, w[0..7]
    float4 hv = *(const float4*)&hnew[b * HH + h0];
    float m = -1e30f, s = 0.f;
    float c0 = 0.f, c1 = 0.f, c2 = 0.f, c3 = 0.f;
    int t0 = chunk * TPC;

    for (int tt = 0; tt < TPC; tt += 8) {
        float4 ev[8];
#pragma unroll
        for (int j = 0; j < 8; j++)
            ev[j] = *(const float4*)&enc[((size_t)(t0 + tt + j) * BB + b) * HH + h0];
        float p[8];
#pragma unroll
        for (int j = 0; j < 8; j++)
            p[j] = hv.x * ev[j].x + hv.y * ev[j].y + hv.z * ev[j].z + hv.w * ev[j].w;
#pragma unroll
        for (int o = 16; o; o >>= 1)
#pragma unroll
            for (int j = 0; j < 8; j++) p[j] += __shfl_xor_sync(0xffffffffu, p[j], o);
        if (lane == 0)
#pragma unroll
            for (int j = 0; j < 8; j++) red[j][wid] = p[j];
        __syncthreads();
        if (tid < 8) {
            float sc = red[tid][0] + red[tid][1] + red[tid][2] + red[tid][3]
                     + red[tid][4] + red[tid][5] + red[tid][6] + red[tid][7];
            score_sh[tid] = sc;
            g_scores[b * TT + t0 + tt + tid] = sc;
        }
        __syncthreads();
        if (tid == 0) {
            float bm = score_sh[0];
#pragma unroll
            for (int j = 1; j < 8; j++) bm = fmaxf(bm, score_sh[j]);
            float newm = fmaxf(m, bm);
            float rs = expf(m - newm);
            float ws = 0.f;
#pragma unroll
            for (int j = 0; j < 8; j++) { float wv = expf(score_sh[j] - newm); bc[1 + j] = wv; ws += wv; }
            s = s * rs + ws;
            m = newm;
            bc[0] = rs;
        }
        __syncthreads();
        float rs = bc[0];
        float w0 = bc[1], w1 = bc[2], w2 = bc[3], w3 = bc[4];
        float w4 = bc[5], w5 = bc[6], w6 = bc[7], w7 = bc[8];
        c0 = c0 * rs; c1 = c1 * rs; c2 = c2 * rs; c3 = c3 * rs;
        c0 += w0 * ev[0].x + w1 * ev[1].x + w2 * ev[2].x + w3 * ev[3].x
            + w4 * ev[4].x + w5 * ev[5].x + w6 * ev[6].x + w7 * ev[7].x;
        c1 += w0 * ev[0].y + w1 * ev[1].y + w2 * ev[2].y + w3 * ev[3].y
            + w4 * ev[4].y + w5 * ev[5].y + w6 * ev[6].y + w7 * ev[7].y;
        c2 += w0 * ev[0].z + w1 * ev[1].z + w2 * ev[2].z + w3 * ev[3].z
            + w4 * ev[4].z + w5 * ev[5].z + w6 * ev[6].z + w7 * ev[7].z;
        c3 += w0 * ev[0].w + w1 * ev[1].w + w2 * ev[2].w + w3 * ev[3].w
            + w4 * ev[4].w + w5 * ev[5].w + w6 * ev[6].w + w7 * ev[7].w;
        __syncthreads();   // protect red[][] reuse next iteration
    }
    *(float4*)&g_cctx[((size_t)chunk * BB + b) * HH + h0] = make_float4(c0, c1, c2, c3);
    if (tid == 0) { g_am[chunk * BB + b] = m; g_as[chunk * BB + b] = s; }
}

// ---------------- attention combine: merge partials, emit attn + interleaved context ----------------
__global__ void k_attn_comb(float* __restrict__ attn_out) {
    int b = blockIdx.x;
    int tid = threadIdx.x;
    float f[NCHUNK];
    float mstar = -1e30f;
#pragma unroll
    for (int c = 0; c < NCHUNK; c++) mstar = fmaxf(mstar, g_am[c * BB + b]);
    float sstar = 0.f;
#pragma unroll
    for (int c = 0; c < NCHUNK; c++) {
        f[c] = expf(g_am[c * BB + b] - mstar);
        sstar += g_as[c * BB + b] * f[c];
    }
    float inv = 1.f / sstar;
    int h0 = tid * 4;
    float a[4] = {0.f, 0.f, 0.f, 0.f};
#pragma unroll
    for (int c = 0; c < NCHUNK; c++) {
        float4 v = *(const float4*)&g_cctx[((size_t)c * BB + b) * HH + h0];
        a[0] += v.x * f[c]; a[1] += v.y * f[c]; a[2] += v.z * f[c]; a[3] += v.w * f[c];
    }
    uint2 v0, v1;
    split2(a[0] * inv, a[1] * inv, v0.x, v0.y);
    split2(a[2] * inv, a[3] * inv, v1.x, v1.y);
    g_xcin[b * 1024 + 512 + tid * 2]     = v0;   // second half (context)
    g_xcin[b * 1024 + 512 + tid * 2 + 1] = v1;
#pragma unroll
    for (int j = 0; j < 4; j++) {
        int t = tid + j * 256;
        attn_out[b * TT + t] = expf(g_scores[b * TT + t] - mstar) * inv;
    }
}

// ---------------- concat combine: sum 16 partials + bias -> tanh -> interleaved pairs ----------------
__global__ void k_comb_concat(const float* __restrict__ concat_b) {
    int i = blockIdx.x * 256 + threadIdx.x;   // B*H/2
    float v2[2];
#pragma unroll
    for (int e = 0; e < 2; e++) {
        int idx = i * 2 + e;
        int n = idx & 1023;
        float v = concat_b[n];
#pragma unroll
        for (int s = 0; s < 16; s++) v += g_cpart[s * BB * HH + idx];
        v2[e] = tanhf(v);
    }
    uint2 v;
    split2(v2[0], v2[1], v.x, v.y);
    g_xcout[i] = v;
}

// ---------------- out combine: 4 partials + bias ----------------
__global__ void k_comb_out(const float* __restrict__ out_b, float* __restrict__ out) {
    int i = blockIdx.x * 256 + threadIdx.x;   // B*V
    int n = i % VV;
    const size_t S = (size_t)BB * VV;
    out[i] = ((g_cpart[i] + g_cpart[S + i]) + (g_cpart[2 * S + i] + g_cpart[3 * S + i])) + out_b[n];
}

// ---------------- launcher ----------------
extern "C" void kernel_launch(void* const* d_in, const int* in_sizes, int n_in,
                              void* d_out, int out_size) {
    const int*   seq         = (const int*)d_in[0];
    const float* last_hidden = (const float*)d_in[1];
    const float* enc         = (const float*)d_in[2];
    const float* emb_table   = (const float*)d_in[3];
    const float* w_ih        = (const float*)d_in[4];
    const float* w_hh        = (const float*)d_in[5];
    const float* b_ih        = (const float*)d_in[6];
    const float* b_hh        = (const float*)d_in[7];
    const float* concat_W    = (const float*)d_in[8];
    const float* concat_b    = (const float*)d_in[9];
    const float* out_W       = (const float*)d_in[10];
    const float* out_b       = (const float*)d_in[11];

    float* out        = (float*)d_out;             // [B, V]
    float* out_hidden = out + BB * VV;             // [1, B, H]
    float* out_attn   = out + BB * VV + BB * HH;   // [B, 1, T]

    float* p_cp;
    uint2 *p_xemb, *p_xhid, *p_xcin, *p_xcout;
    cudaGetSymbolAddress((void**)&p_cp,    g_cpart);
    cudaGetSymbolAddress((void**)&p_xemb,  g_xemb);
    cudaGetSymbolAddress((void**)&p_xhid,  g_xhid);
    cudaGetSymbolAddress((void**)&p_xcin,  g_xcin);
    cudaGetSymbolAddress((void**)&p_xcout, g_xcout);

    float* cpA = p_cp;                                // gx partials [8][B][3H]
    float* cpB = p_cp + 8 * BB * 3 * HH;              // gh partials [8][B][3H]

    // 1. prep: embedding + hidden -> interleaved bf16 hi/lo
    k_prep<<<128, 256>>>(seq, emb_table, last_hidden);
    // 2. gx = emb @ w_ih^T ; gh = h @ w_hh^T  (merged via z, ksplit=8 -> 384 CTAs)
    k_hmma<<<dim3(24, 8, 2), 256>>>(w_ih, w_hh, p_xemb, p_xhid, cpA, cpB, HH);
    // 3. GRU gates -> h_new (folds 8-way partial-combine + bias)
    k_gate<<<128, 256>>>(last_hidden, out_hidden, b_ih, b_hh);
    // 4. fused attention, single enc pass (batched online softmax)
    k_attn<<<dim3(NCHUNK, BB), 256>>>(enc, out_hidden);
    k_attn_comb<<<BB, 256>>>(out_attn);
    // 5. concat gemm (K=2048, ksplit=16 -> 128 CTAs)
    k_hmma<<<dim3(8, 16, 1), 256>>>(concat_W, concat_W, p_xcin, p_xcin, p_cp, p_cp, 2 * HH);
    k_comb_concat<<<128, 256>>>(concat_b);
    // 6. output gemm (K=1024, ksplit=4 -> 1000 CTAs) + combine
    k_hmma<<<dim3(250, 4, 1), 256>>>(out_W, out_W, p_xcout, p_xcout, p_cp, p_cp, HH);
    k_comb_out<<<8000, 256>>>(out_b, out);
}

// round 14
// speedup vs baseline: 1.2884x; 1.0706x over previous
#include <cuda_runtime.h>
#include <cuda_bf16.h>
#include <cstdint>

#define BB 64
#define HH 1024
#define TT 1024
#define VV 32000
#define NCHUNK 32
#define TPC (TT / NCHUNK)

// ---------------- scratch (no allocs allowed) ----------------
__device__ float g_scores[BB * TT];
__device__ float g_am[NCHUNK * BB];
__device__ float g_as[NCHUNK * BB];
__device__ float g_cctx[NCHUNK * BB * HH];
__device__ float g_cpart[4 * BB * VV];                 // partials (gx/gh/concat)
__device__ uint2 g_xemb[BB * HH / 2];                  // interleaved {bf16x2 hi, bf16x2 lo}
__device__ uint2 g_xhid[BB * HH / 2];
__device__ uint2 g_xcin[BB * 2 * HH / 2];
__device__ uint2 g_xcout[BB * HH / 2];

// ---------------- helpers ----------------
__device__ __forceinline__ void split2(float f0, float f1, uint32_t& hi, uint32_t& lo) {
    uint32_t h0 = (uint32_t)__bfloat16_as_ushort(__float2bfloat16(f0));
    uint32_t h1 = (uint32_t)__bfloat16_as_ushort(__float2bfloat16(f1));
    hi = h0 | (h1 << 16);
    float r0 = f0 - __uint_as_float(h0 << 16);
    float r1 = f1 - __uint_as_float(h1 << 16);
    uint32_t l0 = (uint32_t)__bfloat16_as_ushort(__float2bfloat16(r0));
    uint32_t l1 = (uint32_t)__bfloat16_as_ushort(__float2bfloat16(r1));
    lo = l0 | (l1 << 16);
}

#define MMA16816(D, A, B) \
    asm volatile("mma.sync.aligned.m16n8k16.row.col.f32.bf16.bf16.f32 " \
        "{%0,%1,%2,%3}, {%4,%5,%6,%7}, {%8,%9}, {%0,%1,%2,%3};" \
        : "+f"((D)[0]), "+f"((D)[1]), "+f"((D)[2]), "+f"((D)[3]) \
        : "r"((A)[0]), "r"((A)[1]), "r"((A)[2]), "r"((A)[3]), "r"((B)[0]), "r"((B)[1]))

// load 4 float2 of W for one 16-k chunk (16-row warp tile)
#define LOADW(dst, kk) do { \
    const float* p = Wp + (kk); \
    (dst)[0] = *(const float2*)(p); \
    (dst)[1] = *(const float2*)(p + (size_t)8 * K); \
    (dst)[2] = *(const float2*)(p + 8); \
    (dst)[3] = *(const float2*)(p + (size_t)8 * K + 8); \
} while (0)

// global X load: one uint4 (16B) per thread per chunk
#define LDGX(c) (*(const uint4*)&Xp[(size_t)(threadIdx.x >> 2) * K2 + ((k0b + (c) * 16) >> 1) + (threadIdx.x & 3) * 2])

// scatter a chunk's uint4 into fragment-order smem
#define STSX(pb, v) do { \
    int row_ = threadIdx.x >> 2, p4_ = threadIdx.x & 3; \
    int bf_ = row_ >> 3, grp_ = row_ & 7; \
    uint2* b_ = (uint2*)&sb[pb][0]; \
    if (p4_ < 2) { \
        int L_ = bf_ * 32 + grp_ * 4 + p4_ * 2; \
        b_[L_ * 2]       = make_uint2((v).x, (v).y); \
        b_[(L_ + 1) * 2] = make_uint2((v).z, (v).w); \
    } else { \
        int L_ = bf_ * 32 + grp_ * 4 + (p4_ - 2) * 2; \
        b_[L_ * 2 + 1]       = make_uint2((v).x, (v).y); \
        b_[(L_ + 1) * 2 + 1] = make_uint2((v).z, (v).w); \
    } \
} while (0)

// LDS fragments + split W + 24 MMAs (3-term) for one 16-k chunk
#define CHUNK_MMA_S(wsrc, pb) do { \
    uint32_t xh[8][2], xl[8][2]; \
    _Pragma("unroll") \
    for (int bf = 0; bf < 8; bf++) { \
        uint4 v_ = sb[pb][bf * 32 + l]; \
        xh[bf][0] = v_.x; xl[bf][0] = v_.y; \
        xh[bf][1] = v_.z; xl[bf][1] = v_.w; \
    } \
    uint32_t ah[4], al[4]; \
    _Pragma("unroll") \
    for (int j = 0; j < 4; j++) \
        split2((wsrc)[j].x, (wsrc)[j].y, ah[j], al[j]); \
    _Pragma("unroll") \
    for (int bf = 0; bf < 8; bf++) { \
        MMA16816(acc[bf], ah, xh[bf]); \
        MMA16816(acc[bf], ah, xl[bf]); \
        MMA16816(acc[bf], al, xh[bf]); \
    } \
} while (0)

// ---------------- HMMA GEMM: Out[ksplit][b][n] = X[64,K] @ W[N,K]^T (+bias) ----------------
// 8 warps/CTA, warp tile 16n x 64b. X smem-staged (fragment order, 2-deep);
// W register-double-buffered. kpb % 32 == 0.
__global__ void __launch_bounds__(256, 2) k_hmma(
    const float* __restrict__ W0, const float* __restrict__ W1,
    const uint2* __restrict__ X0, const uint2* __restrict__ X1,
    float* __restrict__ Out0, float* __restrict__ Out1,
    const float* __restrict__ bias, int K)
{
    __shared__ uint4 sb[2][256];   // 2 x 4KB chunk buffers, fragment order
    const float* W = blockIdx.z ? W1 : W0;
    const uint2* Xp = blockIdx.z ? X1 : X0;
    float* Out = blockIdx.z ? Out1 : Out0;

    const int Ntot = gridDim.x * 128;
    const int K2 = K >> 1;
    const int w = threadIdx.x >> 5, l = threadIdx.x & 31;
    const int grp = l >> 2, qid = l & 3;
    const int n0 = blockIdx.x * 128 + w * 16;
    const int kpb = K / gridDim.y;
    const int k0b = blockIdx.y * kpb;
    const int nc = kpb >> 4;
    Out += (size_t)blockIdx.y * ((size_t)BB * Ntot);

    float acc[8][4] = {};
    const float* Wp = W + (size_t)(n0 + grp) * K + k0b + qid * 2;

    float2 wcur[4], wnxt[4];
    uint4 xnxt;
    {
        uint4 x0 = LDGX(0);
        STSX(0, x0);
        xnxt = (nc > 1) ? LDGX(1) : x0;
    }
    LOADW(wcur, 0);
    __syncthreads();

    for (int c = 0; c < nc; c++) {
        const int pb = c & 1;
        if (c + 1 < nc) STSX(pb ^ 1, xnxt);
        if (c + 2 < nc) xnxt = LDGX(c + 2);
        if (c + 1 < nc) LOADW(wnxt, (c + 1) * 16);
        CHUNK_MMA_S(wcur, pb);
#pragma unroll
        for (int j = 0; j < 4; j++) wcur[j] = wnxt[j];
        __syncthreads();
    }

    {
        int n = n0 + grp;
        float bv0 = bias ? bias[n] : 0.f;
        float bv8 = bias ? bias[n + 8] : 0.f;
#pragma unroll
        for (int bf = 0; bf < 8; bf++) {
            int b = bf * 8 + qid * 2;
            Out[(size_t)b * Ntot + n]           = acc[bf][0] + bv0;
            Out[(size_t)(b + 1) * Ntot + n]     = acc[bf][1] + bv0;
            Out[(size_t)b * Ntot + n + 8]       = acc[bf][2] + bv8;
            Out[(size_t)(b + 1) * Ntot + n + 8] = acc[bf][3] + bv8;
        }
    }
}

// ---------------- prep: embedding gather + hidden -> interleaved bf16 hi/lo pairs ----------------
__global__ void k_prep(const int* __restrict__ seq, const float* __restrict__ table,
                       const float* __restrict__ last_hidden) {
    int i = blockIdx.x * 256 + threadIdx.x;   // B*H/2 pairs
    int b = i >> 9, hp = i & 511;
    float2 e = *(const float2*)&table[(size_t)seq[b] * HH + hp * 2];
    uint2 v;
    split2(e.x, e.y, v.x, v.y);
    g_xemb[i] = v;
    float2 hd = *(const float2*)&last_hidden[b * HH + hp * 2];
    split2(hd.x, hd.y, v.x, v.y);
    g_xhid[i] = v;
}

// ---------------- GRU gates (4-way partial combine + bias folded), 2 h per thread ----------------
__global__ void k_gate(const float* __restrict__ last_hidden, float* __restrict__ out_hidden,
                       const float* __restrict__ b_ih, const float* __restrict__ b_hh) {
    int i = blockIdx.x * 256 + threadIdx.x;   // B*H/2
    int b = i >> 9, hp = i & 511;
    const float* cpA = g_cpart;                        // gx partials [4][B][3H]
    const float* cpB = g_cpart + 4 * BB * 3 * HH;      // gh partials [4][B][3H]
    const int S = BB * 3 * HH;
    int base = b * 3 * HH;
    float hnew2[2];
#pragma unroll
    for (int e = 0; e < 2; e++) {
        int h = hp * 2 + e;
        float xr = b_ih[h], xz = b_ih[HH + h], xn = b_ih[2 * HH + h];
        float hr = b_hh[h], hz = b_hh[HH + h], hn = b_hh[2 * HH + h];
#pragma unroll
        for (int s = 0; s < 4; s++) {
            xr += cpA[s * S + base + h];
            xz += cpA[s * S + base + HH + h];
            xn += cpA[s * S + base + 2 * HH + h];
            hr += cpB[s * S + base + h];
            hz += cpB[s * S + base + HH + h];
            hn += cpB[s * S + base + 2 * HH + h];
        }
        float r = 1.f / (1.f + expf(-(xr + hr)));
        float z = 1.f / (1.f + expf(-(xz + hz)));
        float n = tanhf(xn + r * hn);
        hnew2[e] = (1.f - z) * n + z * last_hidden[b * HH + h];
        out_hidden[b * HH + h] = hnew2[e];
    }
    uint2 v;
    split2(hnew2[0], hnew2[1], v.x, v.y);
    g_xcin[b * 1024 + hp] = v;     // cin row = 2H -> 1024 pairs; first half
}

// ---------------- fused attention, 8-timestep batched online softmax ----------------
__global__ void __launch_bounds__(256) k_attn(const float* __restrict__ enc, const float* __restrict__ hnew) {
    int chunk = blockIdx.x, b = blockIdx.y;
    int tid = threadIdx.x;
    int wid = tid >> 5, lane = tid & 31;
    int h0 = tid * 4;
    __shared__ float red[8][8];       // [j][warp]
    __shared__ float score_sh[8];
    __shared__ float bc[9];           // rs, w[0..7]
    float4 hv = *(const float4*)&hnew[b * HH + h0];
    float m = -1e30f, s = 0.f;
    float c0 = 0.f, c1 = 0.f, c2 = 0.f, c3 = 0.f;
    int t0 = chunk * TPC;

    for (int tt = 0; tt < TPC; tt += 8) {
        float4 ev[8];
#pragma unroll
        for (int j = 0; j < 8; j++)
            ev[j] = *(const float4*)&enc[((size_t)(t0 + tt + j) * BB + b) * HH + h0];
        float p[8];
#pragma unroll
        for (int j = 0; j < 8; j++)
            p[j] = hv.x * ev[j].x + hv.y * ev[j].y + hv.z * ev[j].z + hv.w * ev[j].w;
#pragma unroll
        for (int o = 16; o; o >>= 1)
#pragma unroll
            for (int j = 0; j < 8; j++) p[j] += __shfl_xor_sync(0xffffffffu, p[j], o);
        if (lane == 0)
#pragma unroll
            for (int j = 0; j < 8; j++) red[j][wid] = p[j];
        __syncthreads();
        if (tid < 8) {
            float sc = red[tid][0] + red[tid][1] + red[tid][2] + red[tid][3]
                     + red[tid][4] + red[tid][5] + red[tid][6] + red[tid][7];
            score_sh[tid] = sc;
            g_scores[b * TT + t0 + tt + tid] = sc;
        }
        __syncthreads();
        if (tid == 0) {
            float bm = score_sh[0];
#pragma unroll
            for (int j = 1; j < 8; j++) bm = fmaxf(bm, score_sh[j]);
            float newm = fmaxf(m, bm);
            float rs = expf(m - newm);
            float ws = 0.f;
#pragma unroll
            for (int j = 0; j < 8; j++) { float wv = expf(score_sh[j] - newm); bc[1 + j] = wv; ws += wv; }
            s = s * rs + ws;
            m = newm;
            bc[0] = rs;
        }
        __syncthreads();
        float rs = bc[0];
        float w0 = bc[1], w1 = bc[2], w2 = bc[3], w3 = bc[4];
        float w4 = bc[5], w5 = bc[6], w6 = bc[7], w7 = bc[8];
        c0 = c0 * rs; c1 = c1 * rs; c2 = c2 * rs; c3 = c3 * rs;
        c0 += w0 * ev[0].x + w1 * ev[1].x + w2 * ev[2].x + w3 * ev[3].x
            + w4 * ev[4].x + w5 * ev[5].x + w6 * ev[6].x + w7 * ev[7].x;
        c1 += w0 * ev[0].y + w1 * ev[1].y + w2 * ev[2].y + w3 * ev[3].y
            + w4 * ev[4].y + w5 * ev[5].y + w6 * ev[6].y + w7 * ev[7].y;
        c2 += w0 * ev[0].z + w1 * ev[1].z + w2 * ev[2].z + w3 * ev[3].z
            + w4 * ev[4].z + w5 * ev[5].z + w6 * ev[6].z + w7 * ev[7].z;
        c3 += w0 * ev[0].w + w1 * ev[1].w + w2 * ev[2].w + w3 * ev[3].w
            + w4 * ev[4].w + w5 * ev[5].w + w6 * ev[6].w + w7 * ev[7].w;
        __syncthreads();   // protect red[][] reuse next iteration
    }
    *(float4*)&g_cctx[((size_t)chunk * BB + b) * HH + h0] = make_float4(c0, c1, c2, c3);
    if (tid == 0) { g_am[chunk * BB + b] = m; g_as[chunk * BB + b] = s; }
}

// ---------------- attention combine: merge partials, emit attn + interleaved context ----------------
__global__ void k_attn_comb(float* __restrict__ attn_out) {
    int b = blockIdx.x;
    int tid = threadIdx.x;
    float f[NCHUNK];
    float mstar = -1e30f;
#pragma unroll
    for (int c = 0; c < NCHUNK; c++) mstar = fmaxf(mstar, g_am[c * BB + b]);
    float sstar = 0.f;
#pragma unroll
    for (int c = 0; c < NCHUNK; c++) {
        f[c] = expf(g_am[c * BB + b] - mstar);
        sstar += g_as[c * BB + b] * f[c];
    }
    float inv = 1.f / sstar;
    int h0 = tid * 4;
    float a[4] = {0.f, 0.f, 0.f, 0.f};
#pragma unroll
    for (int c = 0; c < NCHUNK; c++) {
        float4 v = *(const float4*)&g_cctx[((size_t)c * BB + b) * HH + h0];
        a[0] += v.x * f[c]; a[1] += v.y * f[c]; a[2] += v.z * f[c]; a[3] += v.w * f[c];
    }
    uint2 v0, v1;
    split2(a[0] * inv, a[1] * inv, v0.x, v0.y);
    split2(a[2] * inv, a[3] * inv, v1.x, v1.y);
    g_xcin[b * 1024 + 512 + tid * 2]     = v0;   // second half (context)
    g_xcin[b * 1024 + 512 + tid * 2 + 1] = v1;
#pragma unroll
    for (int j = 0; j < 4; j++) {
        int t = tid + j * 256;
        attn_out[b * TT + t] = expf(g_scores[b * TT + t] - mstar) * inv;
    }
}

// ---------------- concat combine: sum 16 partials + bias -> tanh -> interleaved pairs ----------------
__global__ void k_comb_concat(const float* __restrict__ concat_b) {
    int i = blockIdx.x * 256 + threadIdx.x;   // B*H/2
    float v2[2];
#pragma unroll
    for (int e = 0; e < 2; e++) {
        int idx = i * 2 + e;
        int n = idx & 1023;
        float v = concat_b[n];
#pragma unroll
        for (int s = 0; s < 16; s++) v += g_cpart[s * BB * HH + idx];
        v2[e] = tanhf(v);
    }
    uint2 v;
    split2(v2[0], v2[1], v.x, v.y);
    g_xcout[i] = v;
}

// ---------------- launcher ----------------
extern "C" void kernel_launch(void* const* d_in, const int* in_sizes, int n_in,
                              void* d_out, int out_size) {
    const int*   seq         = (const int*)d_in[0];
    const float* last_hidden = (const float*)d_in[1];
    const float* enc         = (const float*)d_in[2];
    const float* emb_table   = (const float*)d_in[3];
    const float* w_ih        = (const float*)d_in[4];
    const float* w_hh        = (const float*)d_in[5];
    const float* b_ih        = (const float*)d_in[6];
    const float* b_hh        = (const float*)d_in[7];
    const float* concat_W    = (const float*)d_in[8];
    const float* concat_b    = (const float*)d_in[9];
    const float* out_W       = (const float*)d_in[10];
    const float* out_b       = (const float*)d_in[11];

    float* out        = (float*)d_out;             // [B, V]
    float* out_hidden = out + BB * VV;             // [1, B, H]
    float* out_attn   = out + BB * VV + BB * HH;   // [B, 1, T]

    float* p_cp;
    uint2 *p_xemb, *p_xhid, *p_xcin, *p_xcout;
    cudaGetSymbolAddress((void**)&p_cp,    g_cpart);
    cudaGetSymbolAddress((void**)&p_xemb,  g_xemb);
    cudaGetSymbolAddress((void**)&p_xhid,  g_xhid);
    cudaGetSymbolAddress((void**)&p_xcin,  g_xcin);
    cudaGetSymbolAddress((void**)&p_xcout, g_xcout);

    float* cpA = p_cp;                                // gx partials [4][B][3H]
    float* cpB = p_cp + 4 * BB * 3 * HH;              // gh partials [4][B][3H]

    // 1. prep: embedding + hidden -> interleaved bf16 hi/lo
    k_prep<<<128, 256>>>(seq, emb_table, last_hidden);
    // 2. gx = emb @ w_ih^T ; gh = h @ w_hh^T  (merged via z, ksplit=4 -> 192 CTAs)
    k_hmma<<<dim3(24, 4, 2), 256>>>(w_ih, w_hh, p_xemb, p_xhid, cpA, cpB, nullptr, HH);
    // 3. GRU gates -> h_new (folds 4-way partial-combine + bias)
    k_gate<<<128, 256>>>(last_hidden, out_hidden, b_ih, b_hh);
    // 4. fused attention, single enc pass (batched online softmax, 2048 CTAs)
    k_attn<<<dim3(NCHUNK, BB), 256>>>(enc, out_hidden);
    k_attn_comb<<<BB, 256>>>(out_attn);
    // 5. concat gemm (K=2048, ksplit=16 -> 128 CTAs)
    k_hmma<<<dim3(8, 16, 1), 256>>>(concat_W, concat_W, p_xcin, p_xcin, p_cp, p_cp, nullptr, 2 * HH);
    k_comb_concat<<<128, 256>>>(concat_b);
    // 6. output gemm: ksplit=1, single wave (250 CTAs), bias folded, direct write
    k_hmma<<<dim3(250, 1, 1), 256>>>(out_W, out_W, p_xcout, p_xcout, out, out, out_b, HH);
}

// round 15
// speedup vs baseline: 1.2891x; 1.0006x over previous
#include <cuda_runtime.h>
#include <cuda_bf16.h>
#include <cstdint>

#define BB 64
#define HH 1024
#define TT 1024
#define VV 32000
#define NCHUNK 32
#define TPC (TT / NCHUNK)

// ---------------- scratch (no allocs allowed) ----------------
__device__ float g_scores[BB * TT];
__device__ float g_am[NCHUNK * BB];
__device__ float g_as[NCHUNK * BB];
__device__ float g_cctx[NCHUNK * BB * HH];
__device__ float g_cpart[4 * BB * VV];                 // partials (gx/gh/concat)
__device__ uint2 g_xemb[BB * HH / 2];                  // interleaved {bf16x2 hi, bf16x2 lo}
__device__ uint2 g_xhid[BB * HH / 2];
__device__ uint2 g_xcin[BB * 2 * HH / 2];
__device__ uint2 g_xcout[BB * HH / 2];

// ---------------- helpers ----------------
__device__ __forceinline__ void split2(float f0, float f1, uint32_t& hi, uint32_t& lo) {
    uint32_t h0 = (uint32_t)__bfloat16_as_ushort(__float2bfloat16(f0));
    uint32_t h1 = (uint32_t)__bfloat16_as_ushort(__float2bfloat16(f1));
    hi = h0 | (h1 << 16);
    float r0 = f0 - __uint_as_float(h0 << 16);
    float r1 = f1 - __uint_as_float(h1 << 16);
    uint32_t l0 = (uint32_t)__bfloat16_as_ushort(__float2bfloat16(r0));
    uint32_t l1 = (uint32_t)__bfloat16_as_ushort(__float2bfloat16(r1));
    lo = l0 | (l1 << 16);
}

#define MMA16816(D, A, B) \
    asm volatile("mma.sync.aligned.m16n8k16.row.col.f32.bf16.bf16.f32 " \
        "{%0,%1,%2,%3}, {%4,%5,%6,%7}, {%8,%9}, {%0,%1,%2,%3};" \
        : "+f"((D)[0]), "+f"((D)[1]), "+f"((D)[2]), "+f"((D)[3]) \
        : "r"((A)[0]), "r"((A)[1]), "r"((A)[2]), "r"((A)[3]), "r"((B)[0]), "r"((B)[1]))

// load 4 float2 of W for one 16-k chunk (16-row warp tile)
#define LOADW(dst, kk) do { \
    const float* p = Wp + (kk); \
    (dst)[0] = *(const float2*)(p); \
    (dst)[1] = *(const float2*)(p + (size_t)8 * K); \
    (dst)[2] = *(const float2*)(p + 8); \
    (dst)[3] = *(const float2*)(p + (size_t)8 * K + 8); \
} while (0)

// global X load: one uint4 (16B) per thread per chunk (threads 0..255)
#define LDGX(c) (*(const uint4*)&Xp[(size_t)(threadIdx.x >> 2) * K2 + ((k0b + (c) * 16) >> 1) + (threadIdx.x & 3) * 2])

// scatter a chunk's uint4 into fragment-order smem (threads 0..255)
#define STSX(pb, v) do { \
    int row_ = threadIdx.x >> 2, p4_ = threadIdx.x & 3; \
    int bf_ = row_ >> 3, grp_ = row_ & 7; \
    uint2* b_ = (uint2*)&sb[pb][0]; \
    if (p4_ < 2) { \
        int L_ = bf_ * 32 + grp_ * 4 + p4_ * 2; \
        b_[L_ * 2]       = make_uint2((v).x, (v).y); \
        b_[(L_ + 1) * 2] = make_uint2((v).z, (v).w); \
    } else { \
        int L_ = bf_ * 32 + grp_ * 4 + (p4_ - 2) * 2; \
        b_[L_ * 2 + 1]       = make_uint2((v).x, (v).y); \
        b_[(L_ + 1) * 2 + 1] = make_uint2((v).z, (v).w); \
    } \
} while (0)

// LDS fragments + split W + 24 MMAs (3-term) for one 16-k chunk
#define CHUNK_MMA_S(wsrc, pb) do { \
    uint32_t xh[8][2], xl[8][2]; \
    _Pragma("unroll") \
    for (int bf = 0; bf < 8; bf++) { \
        uint4 v_ = sb[pb][bf * 32 + l]; \
        xh[bf][0] = v_.x; xl[bf][0] = v_.y; \
        xh[bf][1] = v_.z; xl[bf][1] = v_.w; \
    } \
    uint32_t ah[4], al[4]; \
    _Pragma("unroll") \
    for (int j = 0; j < 4; j++) \
        split2((wsrc)[j].x, (wsrc)[j].y, ah[j], al[j]); \
    _Pragma("unroll") \
    for (int bf = 0; bf < 8; bf++) { \
        MMA16816(acc[bf], ah, xh[bf]); \
        MMA16816(acc[bf], ah, xl[bf]); \
        MMA16816(acc[bf], al, xh[bf]); \
    } \
} while (0)

// ---------------- HMMA GEMM (128-col tiles): Out[ksplit][b][n] = X[64,K] @ W[N,K]^T ----------------
__global__ void __launch_bounds__(256, 2) k_hmma(
    const float* __restrict__ W0, const float* __restrict__ W1,
    const uint2* __restrict__ X0, const uint2* __restrict__ X1,
    float* __restrict__ Out0, float* __restrict__ Out1,
    const float* __restrict__ bias, int K)
{
    __shared__ uint4 sb[2][256];   // 2 x 4KB chunk buffers, fragment order
    const float* W = blockIdx.z ? W1 : W0;
    const uint2* Xp = blockIdx.z ? X1 : X0;
    float* Out = blockIdx.z ? Out1 : Out0;

    const int Ntot = gridDim.x * 128;
    const int K2 = K >> 1;
    const int w = threadIdx.x >> 5, l = threadIdx.x & 31;
    const int grp = l >> 2, qid = l & 3;
    const int n0 = blockIdx.x * 128 + w * 16;
    const int kpb = K / gridDim.y;
    const int k0b = blockIdx.y * kpb;
    const int nc = kpb >> 4;
    Out += (size_t)blockIdx.y * ((size_t)BB * Ntot);

    float acc[8][4] = {};
    const float* Wp = W + (size_t)(n0 + grp) * K + k0b + qid * 2;

    float2 wcur[4], wnxt[4];
    uint4 xnxt;
    {
        uint4 x0 = LDGX(0);
        STSX(0, x0);
        xnxt = (nc > 1) ? LDGX(1) : x0;
    }
    LOADW(wcur, 0);
    __syncthreads();

    for (int c = 0; c < nc; c++) {
        const int pb = c & 1;
        if (c + 1 < nc) STSX(pb ^ 1, xnxt);
        if (c + 2 < nc) xnxt = LDGX(c + 2);
        if (c + 1 < nc) LOADW(wnxt, (c + 1) * 16);
        CHUNK_MMA_S(wcur, pb);
#pragma unroll
        for (int j = 0; j < 4; j++) wcur[j] = wnxt[j];
        __syncthreads();
    }

    {
        int n = n0 + grp;
        float bv0 = bias ? bias[n] : 0.f;
        float bv8 = bias ? bias[n + 8] : 0.f;
#pragma unroll
        for (int bf = 0; bf < 8; bf++) {
            int b = bf * 8 + qid * 2;
            Out[(size_t)b * Ntot + n]           = acc[bf][0] + bv0;
            Out[(size_t)(b + 1) * Ntot + n]     = acc[bf][1] + bv0;
            Out[(size_t)b * Ntot + n + 8]       = acc[bf][2] + bv8;
            Out[(size_t)(b + 1) * Ntot + n + 8] = acc[bf][3] + bv8;
        }
    }
}

// ---------------- HMMA GEMM (256-col tiles, 512 threads): halves X L2 traffic ----------------
// 16 warps consume one shared X stage; threads 0..255 run the X pipeline.
__global__ void __launch_bounds__(512, 1) k_hmma_wide(
    const float* __restrict__ W, const uint2* __restrict__ Xp,
    float* __restrict__ Out, const float* __restrict__ bias, int K)
{
    __shared__ uint4 sb[2][256];
    const int Ntot = gridDim.x * 256;
    const int K2 = K >> 1;
    const int t = threadIdx.x;
    const int w = t >> 5, l = t & 31;
    const int grp = l >> 2, qid = l & 3;
    const int n0 = blockIdx.x * 256 + w * 16;
    const int k0b = 0;
    const int nc = K >> 4;
    const bool ldr = (t < 256);

    float acc[8][4] = {};
    const float* Wp = W + (size_t)(n0 + grp) * K + qid * 2;

    float2 wcur[4], wnxt[4];
    uint4 xnxt;
    if (ldr) {
        uint4 x0 = LDGX(0);
        STSX(0, x0);
        xnxt = (nc > 1) ? LDGX(1) : x0;
    }
    LOADW(wcur, 0);
    __syncthreads();

    for (int c = 0; c < nc; c++) {
        const int pb = c & 1;
        if (ldr) {
            if (c + 1 < nc) STSX(pb ^ 1, xnxt);
            if (c + 2 < nc) xnxt = LDGX(c + 2);
        }
        if (c + 1 < nc) LOADW(wnxt, (c + 1) * 16);
        CHUNK_MMA_S(wcur, pb);
#pragma unroll
        for (int j = 0; j < 4; j++) wcur[j] = wnxt[j];
        __syncthreads();
    }

    {
        int n = n0 + grp;
        float bv0 = bias ? bias[n] : 0.f;
        float bv8 = bias ? bias[n + 8] : 0.f;
#pragma unroll
        for (int bf = 0; bf < 8; bf++) {
            int b = bf * 8 + qid * 2;
            Out[(size_t)b * Ntot + n]           = acc[bf][0] + bv0;
            Out[(size_t)(b + 1) * Ntot + n]     = acc[bf][1] + bv0;
            Out[(size_t)b * Ntot + n + 8]       = acc[bf][2] + bv8;
            Out[(size_t)(b + 1) * Ntot + n + 8] = acc[bf][3] + bv8;
        }
    }
}

// ---------------- prep: embedding gather + hidden -> interleaved bf16 hi/lo pairs ----------------
__global__ void k_prep(const int* __restrict__ seq, const float* __restrict__ table,
                       const float* __restrict__ last_hidden) {
    int i = blockIdx.x * 256 + threadIdx.x;   // B*H/2 pairs
    int b = i >> 9, hp = i & 511;
    float2 e = *(const float2*)&table[(size_t)seq[b] * HH + hp * 2];
    uint2 v;
    split2(e.x, e.y, v.x, v.y);
    g_xemb[i] = v;
    float2 hd = *(const float2*)&last_hidden[b * HH + hp * 2];
    split2(hd.x, hd.y, v.x, v.y);
    g_xhid[i] = v;
}

// ---------------- GRU gates (4-way partial combine + bias folded), 2 h per thread ----------------
__global__ void k_gate(const float* __restrict__ last_hidden, float* __restrict__ out_hidden,
                       const float* __restrict__ b_ih, const float* __restrict__ b_hh) {
    int i = blockIdx.x * 256 + threadIdx.x;   // B*H/2
    int b = i >> 9, hp = i & 511;
    const float* cpA = g_cpart;                        // gx partials [4][B][3H]
    const float* cpB = g_cpart + 4 * BB * 3 * HH;      // gh partials [4][B][3H]
    const int S = BB * 3 * HH;
    int base = b * 3 * HH;
    float hnew2[2];
#pragma unroll
    for (int e = 0; e < 2; e++) {
        int h = hp * 2 + e;
        float xr = b_ih[h], xz = b_ih[HH + h], xn = b_ih[2 * HH + h];
        float hr = b_hh[h], hz = b_hh[HH + h], hn = b_hh[2 * HH + h];
#pragma unroll
        for (int s = 0; s < 4; s++) {
            xr += cpA[s * S + base + h];
            xz += cpA[s * S + base + HH + h];
            xn += cpA[s * S + base + 2 * HH + h];
            hr += cpB[s * S + base + h];
            hz += cpB[s * S + base + HH + h];
            hn += cpB[s * S + base + 2 * HH + h];
        }
        float r = 1.f / (1.f + expf(-(xr + hr)));
        float z = 1.f / (1.f + expf(-(xz + hz)));
        float n = tanhf(xn + r * hn);
        hnew2[e] = (1.f - z) * n + z * last_hidden[b * HH + h];
        out_hidden[b * HH + h] = hnew2[e];
    }
    uint2 v;
    split2(hnew2[0], hnew2[1], v.x, v.y);
    g_xcin[b * 1024 + hp] = v;     // cin row = 2H -> 1024 pairs; first half
}

// ---------------- fused attention, 8-timestep batch, 2 barriers per batch ----------------
__global__ void __launch_bounds__(256) k_attn(const float* __restrict__ enc, const float* __restrict__ hnew) {
    int chunk = blockIdx.x, b = blockIdx.y;
    int tid = threadIdx.x;
    int wid = tid >> 5, lane = tid & 31;
    int h0 = tid * 4;
    __shared__ float red[8][8];       // [j][warp]
    __shared__ float bc[9];           // rs, w[0..7]
    float4 hv = *(const float4*)&hnew[b * HH + h0];
    float m = -1e30f, s = 0.f;        // meaningful in warp0 lanes 0..7 only
    float c0 = 0.f, c1 = 0.f, c2 = 0.f, c3 = 0.f;
    int t0 = chunk * TPC;

    for (int tt = 0; tt < TPC; tt += 8) {
        float4 ev[8];
#pragma unroll
        for (int j = 0; j < 8; j++)
            ev[j] = *(const float4*)&enc[((size_t)(t0 + tt + j) * BB + b) * HH + h0];
        float p[8];
#pragma unroll
        for (int j = 0; j < 8; j++)
            p[j] = hv.x * ev[j].x + hv.y * ev[j].y + hv.z * ev[j].z + hv.w * ev[j].w;
#pragma unroll
        for (int o = 16; o; o >>= 1)
#pragma unroll
            for (int j = 0; j < 8; j++) p[j] += __shfl_xor_sync(0xffffffffu, p[j], o);
        if (lane == 0)
#pragma unroll
            for (int j = 0; j < 8; j++) red[j][wid] = p[j];
        __syncthreads();                               // (A) red ready
        if (wid == 0) {
            float sc = -1e30f;
            if (lane < 8) {
                sc = ((red[lane][0] + red[lane][1]) + (red[lane][2] + red[lane][3]))
                   + ((red[lane][4] + red[lane][5]) + (red[lane][6] + red[lane][7]));
                g_scores[b * TT + t0 + tt + lane] = sc;
            }
            // max over the 8 scores (within 8-lane group)
            float bm = sc;
#pragma unroll
            for (int o = 4; o; o >>= 1) bm = fmaxf(bm, __shfl_xor_sync(0xffffffffu, bm, o));
            float newm = fmaxf(m, bm);
            float rs = expf(m - newm);
            float wv = expf(sc - newm);                // lanes >=8 -> 0
            float ws = wv;
#pragma unroll
            for (int o = 4; o; o >>= 1) ws += __shfl_xor_sync(0xffffffffu, ws, o);
            s = s * rs + ws;
            m = newm;
            if (lane == 0) bc[0] = rs;
            if (lane < 8) bc[1 + lane] = wv;
        }
        __syncthreads();                               // (B) bc ready; also fences red reuse
        float rs = bc[0];
        float w0 = bc[1], w1 = bc[2], w2 = bc[3], w3 = bc[4];
        float w4 = bc[5], w5 = bc[6], w6 = bc[7], w7 = bc[8];
        c0 = c0 * rs; c1 = c1 * rs; c2 = c2 * rs; c3 = c3 * rs;
        c0 += w0 * ev[0].x + w1 * ev[1].x + w2 * ev[2].x + w3 * ev[3].x
            + w4 * ev[4].x + w5 * ev[5].x + w6 * ev[6].x + w7 * ev[7].x;
        c1 += w0 * ev[0].y + w1 * ev[1].y + w2 * ev[2].y + w3 * ev[3].y
            + w4 * ev[4].y + w5 * ev[5].y + w6 * ev[6].y + w7 * ev[7].y;
        c2 += w0 * ev[0].z + w1 * ev[1].z + w2 * ev[2].z + w3 * ev[3].z
            + w4 * ev[4].z + w5 * ev[5].z + w6 * ev[6].z + w7 * ev[7].z;
        c3 += w0 * ev[0].w + w1 * ev[1].w + w2 * ev[2].w + w3 * ev[3].w
            + w4 * ev[4].w + w5 * ev[5].w + w6 * ev[6].w + w7 * ev[7].w;
    }
    *(float4*)&g_cctx[((size_t)chunk * BB + b) * HH + h0] = make_float4(c0, c1, c2, c3);
    if (tid == 0) { g_am[chunk * BB + b] = m; g_as[chunk * BB + b] = s; }
}

// ---------------- attention combine: merge partials, emit attn + interleaved context ----------------
__global__ void k_attn_comb(float* __restrict__ attn_out) {
    int b = blockIdx.x;
    int tid = threadIdx.x;
    float f[NCHUNK];
    float mstar = -1e30f;
#pragma unroll
    for (int c = 0; c < NCHUNK; c++) mstar = fmaxf(mstar, g_am[c * BB + b]);
    float sstar = 0.f;
#pragma unroll
    for (int c = 0; c < NCHUNK; c++) {
        f[c] = expf(g_am[c * BB + b] - mstar);
        sstar += g_as[c * BB + b] * f[c];
    }
    float inv = 1.f / sstar;
    int h0 = tid * 4;
    float a[4] = {0.f, 0.f, 0.f, 0.f};
#pragma unroll
    for (int c = 0; c < NCHUNK; c++) {
        float4 v = *(const float4*)&g_cctx[((size_t)c * BB + b) * HH + h0];
        a[0] += v.x * f[c]; a[1] += v.y * f[c]; a[2] += v.z * f[c]; a[3] += v.w * f[c];
    }
    uint2 v0, v1;
    split2(a[0] * inv, a[1] * inv, v0.x, v0.y);
    split2(a[2] * inv, a[3] * inv, v1.x, v1.y);
    g_xcin[b * 1024 + 512 + tid * 2]     = v0;   // second half (context)
    g_xcin[b * 1024 + 512 + tid * 2 + 1] = v1;
#pragma unroll
    for (int j = 0; j < 4; j++) {
        int t = tid + j * 256;
        attn_out[b * TT + t] = expf(g_scores[b * TT + t] - mstar) * inv;
    }
}

// ---------------- concat combine: sum 16 partials + bias -> tanh -> interleaved pairs ----------------
__global__ void k_comb_concat(const float* __restrict__ concat_b) {
    int i = blockIdx.x * 256 + threadIdx.x;   // B*H/2
    float v2[2];
#pragma unroll
    for (int e = 0; e < 2; e++) {
        int idx = i * 2 + e;
        int n = idx & 1023;
        float v = concat_b[n];
#pragma unroll
        for (int s = 0; s < 16; s++) v += g_cpart[s * BB * HH + idx];
        v2[e] = tanhf(v);
    }
    uint2 v;
    split2(v2[0], v2[1], v.x, v.y);
    g_xcout[i] = v;
}

// ---------------- launcher ----------------
extern "C" void kernel_launch(void* const* d_in, const int* in_sizes, int n_in,
                              void* d_out, int out_size) {
    const int*   seq         = (const int*)d_in[0];
    const float* last_hidden = (const float*)d_in[1];
    const float* enc         = (const float*)d_in[2];
    const float* emb_table   = (const float*)d_in[3];
    const float* w_ih        = (const float*)d_in[4];
    const float* w_hh        = (const float*)d_in[5];
    const float* b_ih        = (const float*)d_in[6];
    const float* b_hh        = (const float*)d_in[7];
    const float* concat_W    = (const float*)d_in[8];
    const float* concat_b    = (const float*)d_in[9];
    const float* out_W       = (const float*)d_in[10];
    const float* out_b       = (const float*)d_in[11];

    float* out        = (float*)d_out;             // [B, V]
    float* out_hidden = out + BB * VV;             // [1, B, H]
    float* out_attn   = out + BB * VV + BB * HH;   // [B, 1, T]

    float* p_cp;
    uint2 *p_xemb, *p_xhid, *p_xcin, *p_xcout;
    cudaGetSymbolAddress((void**)&p_cp,    g_cpart);
    cudaGetSymbolAddress((void**)&p_xemb,  g_xemb);
    cudaGetSymbolAddress((void**)&p_xhid,  g_xhid);
    cudaGetSymbolAddress((void**)&p_xcin,  g_xcin);
    cudaGetSymbolAddress((void**)&p_xcout, g_xcout);

    float* cpA = p_cp;                                // gx partials [4][B][3H]
    float* cpB = p_cp + 4 * BB * 3 * HH;              // gh partials [4][B][3H]

    // 1. prep: embedding + hidden -> interleaved bf16 hi/lo
    k_prep<<<128, 256>>>(seq, emb_table, last_hidden);
    // 2. gx = emb @ w_ih^T ; gh = h @ w_hh^T  (merged via z, ksplit=4 -> 192 CTAs)
    k_hmma<<<dim3(24, 4, 2), 256>>>(w_ih, w_hh, p_xemb, p_xhid, cpA, cpB, nullptr, HH);
    // 3. GRU gates -> h_new (folds 4-way partial-combine + bias)
    k_gate<<<128, 256>>>(last_hidden, out_hidden, b_ih, b_hh);
    // 4. fused attention, single enc pass (2 barriers per 8-step batch)
    k_attn<<<dim3(NCHUNK, BB), 256>>>(enc, out_hidden);
    k_attn_comb<<<BB, 256>>>(out_attn);
    // 5. concat gemm (K=2048, ksplit=16 -> 128 CTAs)
    k_hmma<<<dim3(8, 16, 1), 256>>>(concat_W, concat_W, p_xcin, p_xcin, p_cp, p_cp, nullptr, 2 * HH);
    k_comb_concat<<<128, 256>>>(concat_b);
    // 6. output gemm: 256-wide tiles, 125 CTAs, halved X L2 traffic, bias folded
    k_hmma_wide<<<125, 512>>>(out_W, p_xcout, out, out_b, HH);
}